// round 13
// baseline (speedup 1.0000x reference)
#include <cuda_runtime.h>
#include <cuda_bf16.h>

// Problem constants (from reference)
#define GX 352
#define GY 400
#define GZ 1
#define BSZ 4
#define NSEG (BSZ * GZ * GY * GX)   // 563200
#define NPTS 2000000
#define CH 4

#define STHR 256
#define NB   ((NPTS + STHR - 1) / STHR)   // 7813 scatter CTAs
#define KFIN 512                           // last-K CTAs run the epilogue
#define SEGS_PER_W (NSEG / KFIN)           // 1100 (exact: 512*1100=563200)

// Output layout: [ mean: NSEG*4 f32 ][ counts: NSEG f32 ]

__device__ unsigned g_done;   // monotonic across replays (each replay adds NB)

// ---- Phase 0: zero output. Fully-resident single wave, trigger-at-top
//      so the scatter launches + prefetches during the fill. ----
#define ZBLK 296
#define ZTHR 256
__global__ void __launch_bounds__(ZTHR)
zero_kernel(float4* __restrict__ out4) {
    cudaTriggerProgrammaticLaunchCompletion();
    const int n4 = (NSEG * CH + NSEG) / 4;            // 704000
    const int stride = ZBLK * ZTHR;
    int i = blockIdx.x * ZTHR + threadIdx.x;
    const float4 z = make_float4(0.f, 0.f, 0.f, 0.f);
#pragma unroll 4
    for (; i < n4; i += stride)
        out4[i] = z;
}

// ---- Phase 1+2: scatter, then work-stealing finalize epilogue.
// Last KFIN CTAs (by arrival order at the done-counter) wait for all REDs
// to be counted, then divide their slice of bins in place. ----
__global__ void __launch_bounds__(STHR)
scatter_kernel(const float4* __restrict__ feats,
               const int4* __restrict__ coors,
               float4* __restrict__ sums,
               float* __restrict__ counts) {
    int i = blockIdx.x * STHR + threadIdx.x;
    int4  c;
    float4 f;
    bool valid = (i < NPTS);
    if (valid) {
        c = coors[i];                                 // independent of bins
        f = feats[i];
    }
    cudaGridDependencySynchronize();                  // zero grid fully done
    if (valid) {
        int seg = ((c.x * GZ + c.y) * GY + c.z) * GX + c.w;
        atomicAdd(&sums[seg], f);                     // RED.128 (L2-resident)
        atomicAdd(&counts[seg], 1.0f);                // RED.32
    }

    // ---- arrival accounting ----
    __threadfence();                                  // make my REDs visible
    __syncthreads();                                  // whole CTA's REDs fenced

    __shared__ unsigned s_pos;
    if (threadIdx.x == 0)
        s_pos = atomicAdd(&g_done, 1u);
    __syncthreads();
    unsigned old  = s_pos;
    unsigned pos  = old % NB;                         // position within this replay
    if (pos < NB - KFIN) return;                      // early CTAs just exit

    // ---- epilogue worker ----
    unsigned base = old - pos;                        // replay round start
    if (threadIdx.x == 0) {
        while (*((volatile unsigned*)&g_done) - base < NB) { }
    }
    __syncthreads();
    __threadfence();                                  // acquire: all REDs visible

    int w    = (int)(pos - (NB - KFIN));              // 0..KFIN-1
    int seg0 = w * SEGS_PER_W;
    int seg1 = seg0 + SEGS_PER_W;
    for (int s = seg0 + threadIdx.x; s < seg1; s += STHR) {
        float cnt = counts[s];
        float inv = 1.0f / fmaxf(cnt, 1.0f);
        float4 v = sums[s];
        v.x *= inv; v.y *= inv; v.z *= inv; v.w *= inv;
        sums[s] = v;                                  // in-place: sums -> mean
    }
}

static inline void launch_pdl(void* func, dim3 grid, dim3 block,
                              void** args, bool pdl) {
    cudaLaunchConfig_t cfg = {};
    cfg.gridDim = grid;
    cfg.blockDim = block;
    cfg.dynamicSmemBytes = 0;
    cfg.stream = 0;                                   // capture (legacy) stream
    cudaLaunchAttribute attr[1];
    if (pdl) {
        attr[0].id = cudaLaunchAttributeProgrammaticStreamSerialization;
        attr[0].val.programmaticStreamSerializationAllowed = 1;
        cfg.attrs = attr;
        cfg.numAttrs = 1;
    }
    cudaLaunchKernelExC(&cfg, func, args);
}

extern "C" void kernel_launch(void* const* d_in, const int* in_sizes, int n_in,
                              void* d_out, int out_size) {
    const float4* feats = (const float4*)d_in[0];     // (NPTS, 4) f32
    const int4*   coors = (const int4*)d_in[1];       // (NPTS, 4) i32
    float* out = (float*)d_out;

    float4* sums   = (float4*)out;                    // NSEG float4
    float*  counts = out + (size_t)NSEG * CH;         // NSEG floats

    // 0) zero output (trigger-at-top, resident wave)
    {
        float4* out4 = (float4*)out;
        void* args[] = { &out4 };
        launch_pdl((void*)zero_kernel, dim3(ZBLK), dim3(ZTHR), args, false);
    }

    // 1) scatter + in-kernel finalize epilogue (PDL on zero)
    {
        void* args[] = { (void*)&feats, (void*)&coors, &sums, &counts };
        launch_pdl((void*)scatter_kernel, dim3(NB), dim3(STHR), args, true);
    }
}

// round 14
// speedup vs baseline: 1.0049x; 1.0049x over previous
#include <cuda_runtime.h>
#include <cuda_bf16.h>

// Problem constants (from reference)
#define GX 352
#define GY 400
#define GZ 1
#define BSZ 4
#define NSEG (BSZ * GZ * GY * GX)   // 563200
#define NPTS 2000000
#define CH 4

#define STHR 256
#define NB   ((NPTS + STHR - 1) / STHR)   // 7813 scatter CTAs
#define KFIN 512                           // last-K CTAs run the epilogue
#define SEGS_PER_W (NSEG / KFIN)           // 1100 (exact: 512*1100=563200)

// Output layout: [ mean: NSEG*4 f32 ][ counts: NSEG f32 ]

__device__ unsigned g_done;   // monotonic across replays (each replay adds NB)

// ---- Phase 0: zero output. Fully-resident single wave, trigger-at-top
//      so the scatter launches + prefetches during the fill. ----
#define ZBLK 296
#define ZTHR 256
__global__ void __launch_bounds__(ZTHR)
zero_kernel(float4* __restrict__ out4) {
    cudaTriggerProgrammaticLaunchCompletion();
    const int n4 = (NSEG * CH + NSEG) / 4;            // 704000
    const int stride = ZBLK * ZTHR;
    int i = blockIdx.x * ZTHR + threadIdx.x;
    const float4 z = make_float4(0.f, 0.f, 0.f, 0.f);
#pragma unroll 4
    for (; i < n4; i += stride)
        out4[i] = z;
}

// ---- Phase 1+2: scatter, then work-stealing finalize epilogue.
// Last KFIN CTAs (by arrival order at the done-counter) wait for all REDs
// to be counted, then divide their slice of bins in place. ----
__global__ void __launch_bounds__(STHR)
scatter_kernel(const float4* __restrict__ feats,
               const int4* __restrict__ coors,
               float4* __restrict__ sums,
               float* __restrict__ counts) {
    int i = blockIdx.x * STHR + threadIdx.x;
    int4  c;
    float4 f;
    bool valid = (i < NPTS);
    if (valid) {
        c = coors[i];                                 // independent of bins
        f = feats[i];
    }
    cudaGridDependencySynchronize();                  // zero grid fully done
    if (valid) {
        int seg = ((c.x * GZ + c.y) * GY + c.z) * GX + c.w;
        atomicAdd(&sums[seg], f);                     // RED.128 (L2-resident)
        atomicAdd(&counts[seg], 1.0f);                // RED.32
    }

    // ---- arrival accounting ----
    __threadfence();                                  // make my REDs visible
    __syncthreads();                                  // whole CTA's REDs fenced

    __shared__ unsigned s_pos;
    if (threadIdx.x == 0)
        s_pos = atomicAdd(&g_done, 1u);
    __syncthreads();
    unsigned old  = s_pos;
    unsigned pos  = old % NB;                         // position within this replay
    if (pos < NB - KFIN) return;                      // early CTAs just exit

    // ---- epilogue worker ----
    unsigned base = old - pos;                        // replay round start
    if (threadIdx.x == 0) {
        while (*((volatile unsigned*)&g_done) - base < NB) { }
    }
    __syncthreads();
    __threadfence();                                  // acquire: all REDs visible

    int w    = (int)(pos - (NB - KFIN));              // 0..KFIN-1
    int seg0 = w * SEGS_PER_W;
    int seg1 = seg0 + SEGS_PER_W;
    for (int s = seg0 + threadIdx.x; s < seg1; s += STHR) {
        float cnt = counts[s];
        float inv = 1.0f / fmaxf(cnt, 1.0f);
        float4 v = sums[s];
        v.x *= inv; v.y *= inv; v.z *= inv; v.w *= inv;
        sums[s] = v;                                  // in-place: sums -> mean
    }
}

static inline void launch_pdl(void* func, dim3 grid, dim3 block,
                              void** args, bool pdl) {
    cudaLaunchConfig_t cfg = {};
    cfg.gridDim = grid;
    cfg.blockDim = block;
    cfg.dynamicSmemBytes = 0;
    cfg.stream = 0;                                   // capture (legacy) stream
    cudaLaunchAttribute attr[1];
    if (pdl) {
        attr[0].id = cudaLaunchAttributeProgrammaticStreamSerialization;
        attr[0].val.programmaticStreamSerializationAllowed = 1;
        cfg.attrs = attr;
        cfg.numAttrs = 1;
    }
    cudaLaunchKernelExC(&cfg, func, args);
}

extern "C" void kernel_launch(void* const* d_in, const int* in_sizes, int n_in,
                              void* d_out, int out_size) {
    const float4* feats = (const float4*)d_in[0];     // (NPTS, 4) f32
    const int4*   coors = (const int4*)d_in[1];       // (NPTS, 4) i32
    float* out = (float*)d_out;

    float4* sums   = (float4*)out;                    // NSEG float4
    float*  counts = out + (size_t)NSEG * CH;         // NSEG floats

    // 0) zero output (trigger-at-top, resident wave)
    {
        float4* out4 = (float4*)out;
        void* args[] = { &out4 };
        launch_pdl((void*)zero_kernel, dim3(ZBLK), dim3(ZTHR), args, false);
    }

    // 1) scatter + in-kernel finalize epilogue (PDL on zero)
    {
        void* args[] = { (void*)&feats, (void*)&coors, &sums, &counts };
        launch_pdl((void*)scatter_kernel, dim3(NB), dim3(STHR), args, true);
    }
}